// round 9
// baseline (speedup 1.0000x reference)
#include <cuda_runtime.h>

#define N_NODES 100000
#define E_EDGES 1000000
#define H_DIM   64
#define OUT_DIM 16
#define R_REL   90
#define B_BAS   8
#define SC_EPB  2048
#define SB_BLKS ((E_EDGES + SC_EPB - 1) / SC_EPB)   // 489

typedef unsigned long long ull;

// ---------------- device scratch ----------------
__device__ float4 g_W40[R_REL * H_DIM * 16];   // quad-interleaved W, layer 0
__device__ float4 g_W41[R_REL * H_DIM * 16];   // quad-interleaved W, layer 1
__device__ float  g_W2[R_REL * H_DIM * OUT_DIM];
__device__ int    g_bh[SB_BLKS * R_REL];
__device__ int    g_off[R_REL + 1];
__device__ int    g_cur[R_REL];
__device__ int4   g_edges[E_EDGES];
__device__ float  g_h1[N_NODES * H_DIM];
__device__ float  g_h2[N_NODES * H_DIM];

#define W64_SZ (R_REL * H_DIM * H_DIM)
#define W16_SZ (R_REL * H_DIM * OUT_DIM)
#define W_TOT  (2 * W64_SZ + W16_SZ)
#define H64Q   (N_NODES * H_DIM / 4)
#define H16Q   (N_NODES * OUT_DIM / 4)
#define FLAT_TOT (2 * H64Q + H16Q + W_TOT)

// ---------------- fused prep: hist + W precompute (quad layout) + init ----
__global__ void __launch_bounds__(256) k_prep(
    const int* __restrict__ et,
    const float* __restrict__ c0, const float* __restrict__ b0,
    const float* __restrict__ c1, const float* __restrict__ b1,
    const float* __restrict__ c2, const float* __restrict__ b2,
    const float* __restrict__ bias0, const float* __restrict__ bias1,
    const float* __restrict__ bias2, float* __restrict__ out)
{
    int b = blockIdx.x;
    int t = threadIdx.x;
    if (b < SB_BLKS) {
        __shared__ int h[R_REL];
        for (int i = t; i < R_REL; i += 256) h[i] = 0;
        __syncthreads();
        int base = b * SC_EPB;
#pragma unroll
        for (int i = 0; i < 8; i++) {
            int e = base + i * 256 + t;
            if (e < E_EDGES) atomicAdd(&h[et[e]], 1);
        }
        __syncthreads();
        for (int i = t; i < R_REL; i += 256)
            g_bh[b * R_REL + i] = h[i];
        return;
    }
    int idx = (b - SB_BLKS) * 256 + t;
    if (idx < H64Q) {
        ((float4*)g_h1)[idx] = ((const float4*)bias0)[idx & 15];
    } else if (idx < 2 * H64Q) {
        int i = idx - H64Q;
        ((float4*)g_h2)[i] = ((const float4*)bias1)[i & 15];
    } else if (idx < 2 * H64Q + H16Q) {
        int i = idx - 2 * H64Q;
        ((float4*)out)[i] = ((const float4*)bias2)[i & 3];
    } else if (idx < FLAT_TOT) {
        int li = idx - (2 * H64Q + H16Q);
        if (li < 2 * W64_SZ) {
            // quad-interleaved: float at [r][i][t][c] = W_r[i][t + c*16]
            const float* coeff = (li < W64_SZ) ? c0 : c1;
            const float* bases = (li < W64_SZ) ? b0 : b1;
            float* W = (li < W64_SZ) ? (float*)g_W40 : (float*)g_W41;
            int lw = (li < W64_SZ) ? li : li - W64_SZ;
            int c  = lw & 3;
            int tt = (lw >> 2) & 15;
            int i  = (lw >> 6) & 63;
            int r  = lw >> 12;
            int o  = tt + c * 16;
            float s = 0.f;
#pragma unroll
            for (int bb = 0; bb < B_BAS; bb++)
                s = fmaf(coeff[r * B_BAS + bb], bases[bb * H_DIM * H_DIM + i * H_DIM + o], s);
            W[lw] = s;
        } else {
            int lw = li - 2 * W64_SZ;
            int r  = lw / (H_DIM * OUT_DIM);
            int io = lw - r * (H_DIM * OUT_DIM);
            float s = 0.f;
#pragma unroll
            for (int bb = 0; bb < B_BAS; bb++)
                s = fmaf(c2[r * B_BAS + bb], b2[bb * H_DIM * OUT_DIM + io], s);
            g_W2[lw] = s;
        }
    }
}

__global__ void k_scan2() {
    __shared__ int tot[R_REL];
    int t = threadIdx.x;
    if (t < R_REL) {
        int s = 0;
        for (int b = 0; b < SB_BLKS; b++) s += g_bh[b * R_REL + t];
        tot[t] = s;
    }
    __syncthreads();
    if (t == 0) {
        int a = 0;
        for (int r = 0; r < R_REL; r++) {
            int c = tot[r]; tot[r] = a; a += c;
        }
        g_off[R_REL] = a;
    }
    __syncthreads();
    if (t < R_REL) {
        g_off[t] = tot[t];
        g_cur[t] = tot[t];
    }
}

__global__ void __launch_bounds__(256) k_scatter(const int* __restrict__ src,
                                                 const int* __restrict__ dst,
                                                 const int* __restrict__ et,
                                                 const float* __restrict__ norm) {
    __shared__ int scnt[R_REL];
    __shared__ int sbase[R_REL];
    int t = threadIdx.x;
    for (int i = t; i < R_REL; i += 256) scnt[i] = 0;
    __syncthreads();
    int base = blockIdx.x * SC_EPB;
    int r[8], rk[8];
#pragma unroll
    for (int i = 0; i < 8; i++) {
        int e = base + i * 256 + t;
        if (e < E_EDGES) {
            r[i]  = et[e];
            rk[i] = atomicAdd(&scnt[r[i]], 1);
        } else r[i] = -1;
    }
    __syncthreads();
    for (int i = t; i < R_REL; i += 256)
        sbase[i] = scnt[i] ? atomicAdd(&g_cur[i], scnt[i]) : 0;
    __syncthreads();
#pragma unroll
    for (int i = 0; i < 8; i++) {
        int e = base + i * 256 + t;
        if (r[i] >= 0) {
            int p = sbase[r[i]] + rk[i];
            g_edges[p] = make_int4(src[e], dst[e], r[i], __float_as_int(norm[e]));
        }
    }
}

// ---------------- f32x2 helpers ----------------
#define FMA2(acc, a, b) \
    asm("fma.rn.f32x2 %0, %1, %2, %0;" : "+l"(acc) : "l"(a), "l"(b))
#define DUP2(d, s) \
    asm("mov.b64 %0, {%1, %1};" : "=l"(d) : "r"(__float_as_uint(s)))
#define UNPK2(f0, f1, s) \
    asm("mov.b64 {%0, %1}, %2;" : "=f"(f0), "=f"(f1) : "l"(s))

// ---------------- edge kernel, H->H: 16 edges/warp, occupancy-3 -----------
// Warp owns 16 edges. Stage x[src]^T (norm & relu folded) into smem tile
// xT[64][16]. Lane = (hh, t): thread owns outs {t,t+16,t+32,t+48} for its
// half's 8 edges, acc = 16 f32x2 (32 regs). Per input i: 1 quad-W LDG.128
// + 2 broadcast LDS.128 + 4 dups + 16 FMA2. Coalesced scalar red epilogue.
#define XS 16
#define XT_WARP (H_DIM * XS)                 // 1024 floats = 4KB

template<bool RELU>
__global__ void __launch_bounds__(256, 3) k_edge64(const float* __restrict__ x,
                                                   const float4* __restrict__ W4,
                                                   float* __restrict__ h) {
    __shared__ float xT[8 * XT_WARP];        // 32KB
    const int tid  = threadIdx.x;
    const int lane = tid & 31;
    const int warp = tid >> 5;
    const int hh   = lane >> 4;
    const int t    = lane & 15;
    float* xw = xT + warp * XT_WARP;

    int blkBase  = blockIdx.x * 128;
    int lim      = min(blkBase + 128, E_EDGES);
    int chunk    = blkBase + warp * 16;
    int chunkEnd = min(chunk + 16, lim);
    if (chunk >= chunkEnd) return;

    // lanes 0..15 hold edge meta for edges chunk+lane
    int  eg  = chunk + lane;
    bool act = (lane < 16) && (eg < chunkEnd);
    int4 ed  = act ? g_edges[eg] : make_int4(0, 0, 0, 0);
    float nrm = act ? __int_as_float(ed.w) : 0.f;

    // stage x^T: 2-lane groups (g = edge, p = half of the 64 inputs)
    {
        int g = lane >> 1, p = lane & 1;
        int   srcE = __shfl_sync(0xffffffffu, ed.x, g);
        float nE   = __shfl_sync(0xffffffffu, nrm, g);
        const float* xr = x + srcE * H_DIM + p * 32;
        float* xc = xw + g;
#pragma unroll
        for (int j = 0; j < 8; j++) {
            float4 v = *(const float4*)(xr + j * 4);
            if (RELU) {
                v.x = fmaxf(v.x, 0.f); v.y = fmaxf(v.y, 0.f);
                v.z = fmaxf(v.z, 0.f); v.w = fmaxf(v.w, 0.f);
            }
            v.x *= nE; v.y *= nE; v.z *= nE; v.w *= nE;
            int i0 = p * 32 + j * 4;
            xc[(i0 + 0) * XS] = v.x;
            xc[(i0 + 1) * XS] = v.y;
            xc[(i0 + 2) * XS] = v.z;
            xc[(i0 + 3) * XS] = v.w;
        }
    }
    __syncwarp();

    int pos = chunk;
    while (pos < chunkEnd) {
        int r      = __shfl_sync(0xffffffffu, ed.z, pos - chunk);
        int segEnd = min(chunkEnd, g_off[r + 1]);
        const float4* Wr = W4 + r * (H_DIM * 16) + t;

        ull acc[16];
#pragma unroll
        for (int j = 0; j < 16; j++) acc[j] = 0ull;

        const float* xb = xw + hh * 8;
#pragma unroll 4
        for (int i = 0; i < H_DIM; i++) {
            float4 w = __ldg(Wr + i * 16);
            ull w0, w1, w2, w3;
            DUP2(w0, w.x); DUP2(w1, w.y); DUP2(w2, w.z); DUP2(w3, w.w);
            const float* xi = xb + i * XS;
            ulonglong2 xv0 = *(const ulonglong2*)(xi);
            ulonglong2 xv1 = *(const ulonglong2*)(xi + 4);
#pragma unroll
            for (int q = 0; q < 4; q++) {
                ull wq = (q == 0) ? w0 : (q == 1) ? w1 : (q == 2) ? w2 : w3;
                FMA2(acc[0 * 4 + q], xv0.x, wq);
                FMA2(acc[1 * 4 + q], xv0.y, wq);
                FMA2(acc[2 * 4 + q], xv1.x, wq);
                FMA2(acc[3 * 4 + q], xv1.y, wq);
            }
        }

        // coalesced scalar reds: per edge, 16 lanes hit consecutive floats
#pragma unroll
        for (int k = 0; k < 16; k++) {
            int gke = chunk + k;
            if (gke < pos || gke >= segEnd) continue;
            int dstE = __shfl_sync(0xffffffffu, ed.y, k);
            if ((k >> 3) == hh) {
                int kk = k & 7, pp = kk >> 1, c = kk & 1;
                float* hp = h + dstE * H_DIM + t;
#pragma unroll
                for (int q = 0; q < 4; q++) {
                    float f0, f1;
                    UNPK2(f0, f1, acc[pp * 4 + q]);
                    float val = c ? f1 : f0;
                    asm volatile("red.global.add.f32 [%0], %1;"
                                 :: "l"(hp + q * 16), "f"(val) : "memory");
                }
            }
        }
        pos = segEnd;
    }
}

// ---------------- edge kernel, H->OUT: thread-per-edge, relu fused ---------
__global__ void __launch_bounds__(256, 4) k_edge16(const float* __restrict__ x,
                                                   const float* __restrict__ W,
                                                   float* __restrict__ h) {
    __shared__ float Ws[H_DIM * OUT_DIM];
    int base = blockIdx.x * 256;
    int lim  = min(base + 256, E_EDGES);
    int pos  = base;
    while (pos < lim) {
        int r      = g_edges[pos].z;
        int segEnd = min(lim, g_off[r + 1]);
        ((float4*)Ws)[threadIdx.x] =
            ((const float4*)(W + r * (H_DIM * OUT_DIM)))[threadIdx.x];
        __syncthreads();

        int e = pos + threadIdx.x;
        if (e < segEnd) {
            int4  ed  = g_edges[e];
            const float* xv = x + ed.x * H_DIM;
            ull acc[8];
#pragma unroll
            for (int j = 0; j < 8; j++) acc[j] = 0ull;

#pragma unroll
            for (int ic = 0; ic < 8; ic++) {
                float4 a0 = *(const float4*)(xv + ic * 8);
                float4 a1 = *(const float4*)(xv + ic * 8 + 4);
                float xs[8] = {a0.x, a0.y, a0.z, a0.w, a1.x, a1.y, a1.z, a1.w};
#pragma unroll
                for (int i = 0; i < 8; i++) {
                    ull A;
                    DUP2(A, fmaxf(xs[i], 0.f) * __int_as_float(ed.w));
                    const float* Wrow = Ws + (ic * 8 + i) * OUT_DIM;
#pragma unroll
                    for (int j = 0; j < 4; j++) {
                        ulonglong2 w = *(const ulonglong2*)(Wrow + j * 4);
                        FMA2(acc[2 * j],     A, w.x);
                        FMA2(acc[2 * j + 1], A, w.y);
                    }
                }
            }

            float* hp = h + ed.y * OUT_DIM;
#pragma unroll
            for (int q = 0; q < 4; q++) {
                float f0, f1, f2, f3;
                UNPK2(f0, f1, acc[2 * q]);
                UNPK2(f2, f3, acc[2 * q + 1]);
                asm volatile("red.global.add.v4.f32 [%0], {%1, %2, %3, %4};"
                             :: "l"(hp + q * 4), "f"(f0), "f"(f1), "f"(f2), "f"(f3)
                             : "memory");
            }
        }
        __syncthreads();
        pos = segEnd;
    }
}

// ---------------- launch ----------------
extern "C" void kernel_launch(void* const* d_in, const int* in_sizes, int n_in,
                              void* d_out, int out_size) {
    const float* feats  = (const float*)d_in[0];
    const float* coeff0 = (const float*)d_in[1];
    const float* bases0 = (const float*)d_in[2];
    const float* bias0  = (const float*)d_in[3];
    const float* coeff1 = (const float*)d_in[4];
    const float* bases1 = (const float*)d_in[5];
    const float* bias1  = (const float*)d_in[6];
    const float* coeff2 = (const float*)d_in[7];
    const float* bases2 = (const float*)d_in[8];
    const float* bias2  = (const float*)d_in[9];
    const int*   src    = (const int*)d_in[10];
    const int*   dst    = (const int*)d_in[11];
    const int*   etype  = (const int*)d_in[12];
    const float* norm   = (const float*)d_in[13];
    float*       out    = (float*)d_out;

    const int EB64 = (E_EDGES + 127) / 128;    // 7813
    const int EB   = (E_EDGES + 255) / 256;
    const int PREP_BLKS = SB_BLKS + (FLAT_TOT + 255) / 256;

    float *h1, *h2, *W2;
    float4 *W40, *W41;
    cudaGetSymbolAddress((void**)&h1,  g_h1);
    cudaGetSymbolAddress((void**)&h2,  g_h2);
    cudaGetSymbolAddress((void**)&W40, g_W40);
    cudaGetSymbolAddress((void**)&W41, g_W41);
    cudaGetSymbolAddress((void**)&W2,  g_W2);

    k_prep<<<PREP_BLKS, 256>>>(etype, coeff0, bases0, coeff1, bases1,
                               coeff2, bases2, bias0, bias1, bias2, out);
    k_scan2<<<1, 128>>>();
    k_scatter<<<SB_BLKS, 256>>>(src, dst, etype, norm);
    // 4th launch -> ncu window
    k_edge64<false><<<EB64, 256>>>(feats, W40, h1);
    k_edge64<true><<<EB64, 256>>>(h1, W41, h2);
    k_edge16<<<EB, 256>>>(h2, W2, out);
}

// round 10
// speedup vs baseline: 1.2868x; 1.2868x over previous
#include <cuda_runtime.h>

#define N_NODES 100000
#define E_EDGES 1000000
#define H_DIM   64
#define OUT_DIM 16
#define R_REL   90
#define B_BAS   8
#define SC_EPB  2048
#define SB_BLKS ((E_EDGES + SC_EPB - 1) / SC_EPB)   // 489

typedef unsigned long long ull;

// ---------------- device scratch ----------------
__device__ float4 g_W40[R_REL * H_DIM * 16];   // quad-interleaved W, layer 0
__device__ float4 g_W41[R_REL * H_DIM * 16];   // quad-interleaved W, layer 1
__device__ float  g_W2[R_REL * H_DIM * OUT_DIM];
__device__ int    g_bh[SB_BLKS * R_REL];
__device__ int    g_off[R_REL + 1];
__device__ int    g_cur[R_REL];
__device__ int4   g_edges[E_EDGES];
__device__ float  g_h1[N_NODES * H_DIM];
__device__ float  g_h2[N_NODES * H_DIM];

#define W64_SZ (R_REL * H_DIM * H_DIM)
#define W16_SZ (R_REL * H_DIM * OUT_DIM)
#define W_TOT  (2 * W64_SZ + W16_SZ)
#define H64Q   (N_NODES * H_DIM / 4)
#define H16Q   (N_NODES * OUT_DIM / 4)
#define FLAT_TOT (2 * H64Q + H16Q + W_TOT)

// ---------------- fused prep: hist + W precompute (quad layout) + init ----
__global__ void __launch_bounds__(256) k_prep(
    const int* __restrict__ et,
    const float* __restrict__ c0, const float* __restrict__ b0,
    const float* __restrict__ c1, const float* __restrict__ b1,
    const float* __restrict__ c2, const float* __restrict__ b2,
    const float* __restrict__ bias0, const float* __restrict__ bias1,
    const float* __restrict__ bias2, float* __restrict__ out)
{
    int b = blockIdx.x;
    int t = threadIdx.x;
    if (b < SB_BLKS) {
        __shared__ int h[R_REL];
        for (int i = t; i < R_REL; i += 256) h[i] = 0;
        __syncthreads();
        int base = b * SC_EPB;
#pragma unroll
        for (int i = 0; i < 8; i++) {
            int e = base + i * 256 + t;
            if (e < E_EDGES) atomicAdd(&h[et[e]], 1);
        }
        __syncthreads();
        for (int i = t; i < R_REL; i += 256)
            g_bh[b * R_REL + i] = h[i];
        return;
    }
    int idx = (b - SB_BLKS) * 256 + t;
    if (idx < H64Q) {
        ((float4*)g_h1)[idx] = ((const float4*)bias0)[idx & 15];
    } else if (idx < 2 * H64Q) {
        int i = idx - H64Q;
        ((float4*)g_h2)[i] = ((const float4*)bias1)[i & 15];
    } else if (idx < 2 * H64Q + H16Q) {
        int i = idx - 2 * H64Q;
        ((float4*)out)[i] = ((const float4*)bias2)[i & 3];
    } else if (idx < FLAT_TOT) {
        int li = idx - (2 * H64Q + H16Q);
        if (li < 2 * W64_SZ) {
            // quad-interleaved: float at [r][i][t][c] = W_r[i][t + c*16]
            const float* coeff = (li < W64_SZ) ? c0 : c1;
            const float* bases = (li < W64_SZ) ? b0 : b1;
            float* W = (li < W64_SZ) ? (float*)g_W40 : (float*)g_W41;
            int lw = (li < W64_SZ) ? li : li - W64_SZ;
            int c  = lw & 3;
            int tt = (lw >> 2) & 15;
            int i  = (lw >> 6) & 63;
            int r  = lw >> 12;
            int o  = tt + c * 16;
            float s = 0.f;
#pragma unroll
            for (int bb = 0; bb < B_BAS; bb++)
                s = fmaf(coeff[r * B_BAS + bb], bases[bb * H_DIM * H_DIM + i * H_DIM + o], s);
            W[lw] = s;
        } else {
            int lw = li - 2 * W64_SZ;
            int r  = lw / (H_DIM * OUT_DIM);
            int io = lw - r * (H_DIM * OUT_DIM);
            float s = 0.f;
#pragma unroll
            for (int bb = 0; bb < B_BAS; bb++)
                s = fmaf(c2[r * B_BAS + bb], b2[bb * H_DIM * OUT_DIM + io], s);
            g_W2[lw] = s;
        }
    }
}

__global__ void k_scan2() {
    __shared__ int tot[R_REL];
    int t = threadIdx.x;
    if (t < R_REL) {
        int s = 0;
        for (int b = 0; b < SB_BLKS; b++) s += g_bh[b * R_REL + t];
        tot[t] = s;
    }
    __syncthreads();
    if (t == 0) {
        int a = 0;
        for (int r = 0; r < R_REL; r++) {
            int c = tot[r]; tot[r] = a; a += c;
        }
        g_off[R_REL] = a;
    }
    __syncthreads();
    if (t < R_REL) {
        g_off[t] = tot[t];
        g_cur[t] = tot[t];
    }
}

__global__ void __launch_bounds__(256) k_scatter(const int* __restrict__ src,
                                                 const int* __restrict__ dst,
                                                 const int* __restrict__ et,
                                                 const float* __restrict__ norm) {
    __shared__ int scnt[R_REL];
    __shared__ int sbase[R_REL];
    int t = threadIdx.x;
    for (int i = t; i < R_REL; i += 256) scnt[i] = 0;
    __syncthreads();
    int base = blockIdx.x * SC_EPB;
    int r[8], rk[8];
#pragma unroll
    for (int i = 0; i < 8; i++) {
        int e = base + i * 256 + t;
        if (e < E_EDGES) {
            r[i]  = et[e];
            rk[i] = atomicAdd(&scnt[r[i]], 1);
        } else r[i] = -1;
    }
    __syncthreads();
    for (int i = t; i < R_REL; i += 256)
        sbase[i] = scnt[i] ? atomicAdd(&g_cur[i], scnt[i]) : 0;
    __syncthreads();
#pragma unroll
    for (int i = 0; i < 8; i++) {
        int e = base + i * 256 + t;
        if (r[i] >= 0) {
            int p = sbase[r[i]] + rk[i];
            g_edges[p] = make_int4(src[e], dst[e], r[i], __float_as_int(norm[e]));
        }
    }
}

// ---------------- f32x2 helpers ----------------
#define FMA2(acc, a, b) \
    asm("fma.rn.f32x2 %0, %1, %2, %0;" : "+l"(acc) : "l"(a), "l"(b))
#define DUP2(d, s) \
    asm("mov.b64 %0, {%1, %1};" : "=l"(d) : "r"(__float_as_uint(s)))
#define UNPK2(f0, f1, s) \
    asm("mov.b64 {%0, %1}, %2;" : "=f"(f0), "=f"(f1) : "l"(s))

// ---------------- edge kernel, H->H: R8 layout + W_r staged in SMEM -------
// Warp owns 32 edges (x^T staged per-warp, norm/relu folded). Block-level
// segment loop: per relation segment, all 256 threads stage the 16KB quad-W
// slice into SMEM (removes L2-miss latency from the inner loop), then each
// warp computes its 32-edge tile: per input i, 1 LDS.128 (quad-W, 2wf
// conflict-free) + 4 broadcast LDS.128 (x) + 32 FMA2. Masked coalesced
// scalar-red epilogue.
#define XT_STRIDE 36
#define XT_WARP   (H_DIM * XT_STRIDE)           // 2304 floats
#define SMEM_E64  (8 * XT_WARP * 4 + H_DIM * 16 * 16)   // 73728 + 16384 = 90112

template<bool RELU>
__global__ void __launch_bounds__(256, 2) k_edge64(const float* __restrict__ x,
                                                   const float4* __restrict__ W4,
                                                   float* __restrict__ h) {
    extern __shared__ float smem[];
    float*  xT  = smem;                              // 8 * XT_WARP floats
    float4* W4s = (float4*)(smem + 8 * XT_WARP);     // 1024 float4 = 16KB

    const int tid  = threadIdx.x;
    const int lane = tid & 31;
    const int warp = tid >> 5;
    const int hh   = lane >> 4;
    const int t    = lane & 15;
    float* xw = xT + warp * XT_WARP;

    int blkBase  = blockIdx.x * 256;
    int lim      = min(blkBase + 256, E_EDGES);
    int chunk    = blkBase + warp * 32;
    int chunkEnd = min(chunk + 32, lim);
    bool hasWork = chunk < chunkEnd;

    // per-lane edge meta (lane -> edge chunk+lane)
    int  eg  = chunk + lane;
    bool act = hasWork && (eg < chunkEnd);
    int4 ed  = act ? g_edges[eg] : make_int4(0, 0, 0, 0);
    float nrm = act ? __int_as_float(ed.w) : 0.f;

    // stage x^T: 4-lane groups cooperatively load one edge row per round
    if (hasWork) {
        int p = lane & 3;
        int g = lane >> 2;
#pragma unroll
        for (int rr = 0; rr < 4; rr++) {
            int e = rr * 8 + g;
            int   srcE = __shfl_sync(0xffffffffu, ed.x, e);
            float nE   = __shfl_sync(0xffffffffu, nrm, e);
            const float* xr = x + srcE * H_DIM;
#pragma unroll
            for (int j = 0; j < 4; j++) {
                float4 v = *(const float4*)(xr + p * 4 + 16 * j);
                if (RELU) {
                    v.x = fmaxf(v.x, 0.f); v.y = fmaxf(v.y, 0.f);
                    v.z = fmaxf(v.z, 0.f); v.w = fmaxf(v.w, 0.f);
                }
                v.x *= nE; v.y *= nE; v.z *= nE; v.w *= nE;
                int i0 = p * 4 + 16 * j;
                xw[(i0 + 0) * XT_STRIDE + e] = v.x;
                xw[(i0 + 1) * XT_STRIDE + e] = v.y;
                xw[(i0 + 2) * XT_STRIDE + e] = v.z;
                xw[(i0 + 3) * XT_STRIDE + e] = v.w;
            }
        }
    }

    // block-level segment loop (pos/lim uniform across the block)
    int pos = blkBase;
    while (pos < lim) {
        int r      = ((const int*)g_edges)[pos * 4 + 2];   // uniform read
        int segEnd = min(lim, g_off[r + 1]);

        __syncthreads();   // previous segment's readers done before overwrite
#pragma unroll
        for (int k = 0; k < 4; k++)
            W4s[tid + k * 256] = W4[r * (H_DIM * 16) + tid + k * 256];
        __syncthreads();

        if (hasWork && chunk < segEnd && chunkEnd > pos) {
            ull acc[32];
#pragma unroll
            for (int j = 0; j < 32; j++) acc[j] = 0ull;

            const float* xb = xw + hh * 16;
#pragma unroll 4
            for (int i = 0; i < H_DIM; i++) {
                float4 w = W4s[i * 16 + t];            // LDS.128, 2wf
                ull w0, w1, w2, w3;
                DUP2(w0, w.x); DUP2(w1, w.y); DUP2(w2, w.z); DUP2(w3, w.w);
                const float* xi = xb + i * XT_STRIDE;
#pragma unroll
                for (int q = 0; q < 4; q++) {
                    ulonglong2 xv = *(const ulonglong2*)(xi + q * 4);
                    FMA2(acc[(2 * q) * 4 + 0], xv.x, w0);
                    FMA2(acc[(2 * q) * 4 + 1], xv.x, w1);
                    FMA2(acc[(2 * q) * 4 + 2], xv.x, w2);
                    FMA2(acc[(2 * q) * 4 + 3], xv.x, w3);
                    FMA2(acc[(2 * q + 1) * 4 + 0], xv.y, w0);
                    FMA2(acc[(2 * q + 1) * 4 + 1], xv.y, w1);
                    FMA2(acc[(2 * q + 1) * 4 + 2], xv.y, w2);
                    FMA2(acc[(2 * q + 1) * 4 + 3], xv.y, w3);
                }
            }

            // masked coalesced scalar reds
#pragma unroll
            for (int k = 0; k < 16; k++) {
                int  le   = hh * 16 + k;
                int  gke  = chunk + le;
                int  dstE = __shfl_sync(0xffffffffu, ed.y, le);
                bool doit = (gke >= pos) && (gke < segEnd);
                if (doit) {
                    float* hp = h + dstE * H_DIM + t;
                    int pp = k >> 1, c = k & 1;
#pragma unroll
                    for (int q = 0; q < 4; q++) {
                        float f0, f1;
                        UNPK2(f0, f1, acc[pp * 4 + q]);
                        float val = c ? f1 : f0;
                        asm volatile("red.global.add.f32 [%0], %1;"
                                     :: "l"(hp + q * 16), "f"(val) : "memory");
                    }
                }
            }
        }
        pos = segEnd;
    }
}

// ---------------- edge kernel, H->OUT: thread-per-edge, relu fused ---------
__global__ void __launch_bounds__(256, 4) k_edge16(const float* __restrict__ x,
                                                   const float* __restrict__ W,
                                                   float* __restrict__ h) {
    __shared__ float Ws[H_DIM * OUT_DIM];
    int base = blockIdx.x * 256;
    int lim  = min(base + 256, E_EDGES);
    int pos  = base;
    while (pos < lim) {
        int r      = g_edges[pos].z;
        int segEnd = min(lim, g_off[r + 1]);
        ((float4*)Ws)[threadIdx.x] =
            ((const float4*)(W + r * (H_DIM * OUT_DIM)))[threadIdx.x];
        __syncthreads();

        int e = pos + threadIdx.x;
        if (e < segEnd) {
            int4  ed  = g_edges[e];
            const float* xv = x + ed.x * H_DIM;
            ull acc[8];
#pragma unroll
            for (int j = 0; j < 8; j++) acc[j] = 0ull;

#pragma unroll
            for (int ic = 0; ic < 8; ic++) {
                float4 a0 = *(const float4*)(xv + ic * 8);
                float4 a1 = *(const float4*)(xv + ic * 8 + 4);
                float xs[8] = {a0.x, a0.y, a0.z, a0.w, a1.x, a1.y, a1.z, a1.w};
#pragma unroll
                for (int i = 0; i < 8; i++) {
                    ull A;
                    DUP2(A, fmaxf(xs[i], 0.f) * __int_as_float(ed.w));
                    const float* Wrow = Ws + (ic * 8 + i) * OUT_DIM;
#pragma unroll
                    for (int j = 0; j < 4; j++) {
                        ulonglong2 w = *(const ulonglong2*)(Wrow + j * 4);
                        FMA2(acc[2 * j],     A, w.x);
                        FMA2(acc[2 * j + 1], A, w.y);
                    }
                }
            }

            float* hp = h + ed.y * OUT_DIM;
#pragma unroll
            for (int q = 0; q < 4; q++) {
                float f0, f1, f2, f3;
                UNPK2(f0, f1, acc[2 * q]);
                UNPK2(f2, f3, acc[2 * q + 1]);
                asm volatile("red.global.add.v4.f32 [%0], {%1, %2, %3, %4};"
                             :: "l"(hp + q * 4), "f"(f0), "f"(f1), "f"(f2), "f"(f3)
                             : "memory");
            }
        }
        __syncthreads();
        pos = segEnd;
    }
}

// ---------------- launch ----------------
extern "C" void kernel_launch(void* const* d_in, const int* in_sizes, int n_in,
                              void* d_out, int out_size) {
    const float* feats  = (const float*)d_in[0];
    const float* coeff0 = (const float*)d_in[1];
    const float* bases0 = (const float*)d_in[2];
    const float* bias0  = (const float*)d_in[3];
    const float* coeff1 = (const float*)d_in[4];
    const float* bases1 = (const float*)d_in[5];
    const float* bias1  = (const float*)d_in[6];
    const float* coeff2 = (const float*)d_in[7];
    const float* bases2 = (const float*)d_in[8];
    const float* bias2  = (const float*)d_in[9];
    const int*   src    = (const int*)d_in[10];
    const int*   dst    = (const int*)d_in[11];
    const int*   etype  = (const int*)d_in[12];
    const float* norm   = (const float*)d_in[13];
    float*       out    = (float*)d_out;

    const int EB = (E_EDGES + 255) / 256;
    const int PREP_BLKS = SB_BLKS + (FLAT_TOT + 255) / 256;

    float *h1, *h2, *W2;
    float4 *W40, *W41;
    cudaGetSymbolAddress((void**)&h1,  g_h1);
    cudaGetSymbolAddress((void**)&h2,  g_h2);
    cudaGetSymbolAddress((void**)&W40, g_W40);
    cudaGetSymbolAddress((void**)&W41, g_W41);
    cudaGetSymbolAddress((void**)&W2,  g_W2);

    cudaFuncSetAttribute(k_edge64<false>,
                         cudaFuncAttributeMaxDynamicSharedMemorySize, SMEM_E64);
    cudaFuncSetAttribute(k_edge64<true>,
                         cudaFuncAttributeMaxDynamicSharedMemorySize, SMEM_E64);

    k_prep<<<PREP_BLKS, 256>>>(etype, coeff0, bases0, coeff1, bases1,
                               coeff2, bases2, bias0, bias1, bias2, out);
    k_scan2<<<1, 128>>>();
    k_scatter<<<SB_BLKS, 256>>>(src, dst, etype, norm);
    // 4th launch -> ncu window
    k_edge64<false><<<EB, 256, SMEM_E64>>>(feats, W40, h1);
    k_edge64<true><<<EB, 256, SMEM_E64>>>(h1, W41, h2);
    k_edge16<<<EB, 256>>>(h2, W2, out);
}

// round 12
// speedup vs baseline: 1.3336x; 1.0364x over previous
#include <cuda_runtime.h>

#define N_NODES 100000
#define E_EDGES 1000000
#define H_DIM   64
#define OUT_DIM 16
#define R_REL   90
#define B_BAS   8
#define SC_EPB  2048
#define SB_BLKS ((E_EDGES + SC_EPB - 1) / SC_EPB)   // 489

typedef unsigned long long ull;

// ---------------- device scratch ----------------
__device__ float4 g_W40[R_REL * H_DIM * 16];   // quad-interleaved W, layer 0
__device__ float4 g_W41[R_REL * H_DIM * 16];   // quad-interleaved W, layer 1
__device__ float  g_W2[R_REL * H_DIM * OUT_DIM];
__device__ int    g_bh[SB_BLKS * R_REL];
__device__ int    g_off[R_REL + 1];
__device__ int    g_cur[R_REL];
__device__ int4   g_edges[E_EDGES];
__device__ float  g_h1[N_NODES * H_DIM];
__device__ float  g_h2[N_NODES * H_DIM];

#define W64_SZ (R_REL * H_DIM * H_DIM)
#define W16_SZ (R_REL * H_DIM * OUT_DIM)
#define W_TOT  (2 * W64_SZ + W16_SZ)
#define H64Q   (N_NODES * H_DIM / 4)
#define H16Q   (N_NODES * OUT_DIM / 4)
#define FLAT_TOT (2 * H64Q + H16Q + W_TOT)

// ---------------- fused prep: hist + W precompute (quad layout) + init ----
__global__ void __launch_bounds__(256) k_prep(
    const int* __restrict__ et,
    const float* __restrict__ c0, const float* __restrict__ b0,
    const float* __restrict__ c1, const float* __restrict__ b1,
    const float* __restrict__ c2, const float* __restrict__ b2,
    const float* __restrict__ bias0, const float* __restrict__ bias1,
    const float* __restrict__ bias2, float* __restrict__ out)
{
    int b = blockIdx.x;
    int t = threadIdx.x;
    if (b < SB_BLKS) {
        __shared__ int h[R_REL];
        for (int i = t; i < R_REL; i += 256) h[i] = 0;
        __syncthreads();
        int base = b * SC_EPB;
#pragma unroll
        for (int i = 0; i < 8; i++) {
            int e = base + i * 256 + t;
            if (e < E_EDGES) atomicAdd(&h[et[e]], 1);
        }
        __syncthreads();
        for (int i = t; i < R_REL; i += 256)
            g_bh[b * R_REL + i] = h[i];
        return;
    }
    int idx = (b - SB_BLKS) * 256 + t;
    if (idx < H64Q) {
        ((float4*)g_h1)[idx] = ((const float4*)bias0)[idx & 15];
    } else if (idx < 2 * H64Q) {
        int i = idx - H64Q;
        ((float4*)g_h2)[i] = ((const float4*)bias1)[i & 15];
    } else if (idx < 2 * H64Q + H16Q) {
        int i = idx - 2 * H64Q;
        ((float4*)out)[i] = ((const float4*)bias2)[i & 3];
    } else if (idx < FLAT_TOT) {
        int li = idx - (2 * H64Q + H16Q);
        if (li < 2 * W64_SZ) {
            // quad-interleaved: float at [r][i][t][c] = W_r[i][t + c*16]
            const float* coeff = (li < W64_SZ) ? c0 : c1;
            const float* bases = (li < W64_SZ) ? b0 : b1;
            float* W = (li < W64_SZ) ? (float*)g_W40 : (float*)g_W41;
            int lw = (li < W64_SZ) ? li : li - W64_SZ;
            int c  = lw & 3;
            int tt = (lw >> 2) & 15;
            int i  = (lw >> 6) & 63;
            int r  = lw >> 12;
            int o  = tt + c * 16;
            float s = 0.f;
#pragma unroll
            for (int bb = 0; bb < B_BAS; bb++)
                s = fmaf(coeff[r * B_BAS + bb], bases[bb * H_DIM * H_DIM + i * H_DIM + o], s);
            W[lw] = s;
        } else {
            int lw = li - 2 * W64_SZ;
            int r  = lw / (H_DIM * OUT_DIM);
            int io = lw - r * (H_DIM * OUT_DIM);
            float s = 0.f;
#pragma unroll
            for (int bb = 0; bb < B_BAS; bb++)
                s = fmaf(c2[r * B_BAS + bb], b2[bb * H_DIM * OUT_DIM + io], s);
            g_W2[lw] = s;
        }
    }
}

// ---------------- scan: parallel reduce of block hists, prefix ------------
__global__ void __launch_bounds__(1024) k_scan2() {
    __shared__ int tot[R_REL];
    int t = threadIdx.x;
    if (t < R_REL) tot[t] = 0;
    __syncthreads();
    if (t < R_REL * 11) {
        int r = t / 11, k = t % 11;
        int s = 0;
        for (int b = k; b < SB_BLKS; b += 11) s += g_bh[b * R_REL + r];
        if (s) atomicAdd(&tot[r], s);
    }
    __syncthreads();
    if (t == 0) {
        int a = 0;
        for (int r = 0; r < R_REL; r++) {
            int c = tot[r]; tot[r] = a; a += c;
        }
        g_off[R_REL] = a;
    }
    __syncthreads();
    if (t < R_REL) {
        g_off[t] = tot[t];
        g_cur[t] = tot[t];
    }
}

__global__ void __launch_bounds__(256) k_scatter(const int* __restrict__ src,
                                                 const int* __restrict__ dst,
                                                 const int* __restrict__ et,
                                                 const float* __restrict__ norm) {
    __shared__ int scnt[R_REL];
    __shared__ int sbase[R_REL];
    int t = threadIdx.x;
    for (int i = t; i < R_REL; i += 256) scnt[i] = 0;
    __syncthreads();
    int base = blockIdx.x * SC_EPB;
    int r[8], rk[8];
#pragma unroll
    for (int i = 0; i < 8; i++) {
        int e = base + i * 256 + t;
        if (e < E_EDGES) {
            r[i]  = et[e];
            rk[i] = atomicAdd(&scnt[r[i]], 1);
        } else r[i] = -1;
    }
    __syncthreads();
    for (int i = t; i < R_REL; i += 256)
        sbase[i] = scnt[i] ? atomicAdd(&g_cur[i], scnt[i]) : 0;
    __syncthreads();
#pragma unroll
    for (int i = 0; i < 8; i++) {
        int e = base + i * 256 + t;
        if (r[i] >= 0) {
            int p = sbase[r[i]] + rk[i];
            g_edges[p] = make_int4(src[e], dst[e], r[i], __float_as_int(norm[e]));
        }
    }
}

// ---------------- f32x2 helpers ----------------
#define FMA2(acc, a, b) \
    asm("fma.rn.f32x2 %0, %1, %2, %0;" : "+l"(acc) : "l"(a), "l"(b))
#define MUL2(acc, b) \
    asm("mul.rn.f32x2 %0, %0, %1;" : "+l"(acc) : "l"(b))
#define DUP2(d, s) \
    asm("mov.b64 %0, {%1, %1};" : "=l"(d) : "r"(__float_as_uint(s)))
#define UNPK2(f0, f1, s) \
    asm("mov.b64 {%0, %1}, %2;" : "=f"(f0), "=f"(f1) : "l"(s))

// ---------------- edge kernel, H->H: R10 (frozen) --------------------------
#define XT_STRIDE 36
#define XT_WARP   (H_DIM * XT_STRIDE)           // 2304 floats
#define SMEM_E64  (8 * XT_WARP * 4 + H_DIM * 16 * 16)   // 90112

template<bool RELU>
__global__ void __launch_bounds__(256, 2) k_edge64(const float* __restrict__ x,
                                                   const float4* __restrict__ W4,
                                                   float* __restrict__ h) {
    extern __shared__ float smem[];
    float*  xT  = smem;
    float4* W4s = (float4*)(smem + 8 * XT_WARP);

    const int tid  = threadIdx.x;
    const int lane = tid & 31;
    const int warp = tid >> 5;
    const int hh   = lane >> 4;
    const int t    = lane & 15;
    float* xw = xT + warp * XT_WARP;

    int blkBase  = blockIdx.x * 256;
    int lim      = min(blkBase + 256, E_EDGES);
    int chunk    = blkBase + warp * 32;
    int chunkEnd = min(chunk + 32, lim);
    bool hasWork = chunk < chunkEnd;

    int  eg  = chunk + lane;
    bool act = hasWork && (eg < chunkEnd);
    int4 ed  = act ? g_edges[eg] : make_int4(0, 0, 0, 0);
    float nrm = act ? __int_as_float(ed.w) : 0.f;

    if (hasWork) {
        int p = lane & 3;
        int g = lane >> 2;
#pragma unroll
        for (int rr = 0; rr < 4; rr++) {
            int e = rr * 8 + g;
            int   srcE = __shfl_sync(0xffffffffu, ed.x, e);
            float nE   = __shfl_sync(0xffffffffu, nrm, e);
            const float* xr = x + srcE * H_DIM;
#pragma unroll
            for (int j = 0; j < 4; j++) {
                float4 v = *(const float4*)(xr + p * 4 + 16 * j);
                if (RELU) {
                    v.x = fmaxf(v.x, 0.f); v.y = fmaxf(v.y, 0.f);
                    v.z = fmaxf(v.z, 0.f); v.w = fmaxf(v.w, 0.f);
                }
                v.x *= nE; v.y *= nE; v.z *= nE; v.w *= nE;
                int i0 = p * 4 + 16 * j;
                xw[(i0 + 0) * XT_STRIDE + e] = v.x;
                xw[(i0 + 1) * XT_STRIDE + e] = v.y;
                xw[(i0 + 2) * XT_STRIDE + e] = v.z;
                xw[(i0 + 3) * XT_STRIDE + e] = v.w;
            }
        }
    }

    int pos = blkBase;
    while (pos < lim) {
        int r      = ((const int*)g_edges)[pos * 4 + 2];
        int segEnd = min(lim, g_off[r + 1]);

        __syncthreads();
#pragma unroll
        for (int k = 0; k < 4; k++)
            W4s[tid + k * 256] = W4[r * (H_DIM * 16) + tid + k * 256];
        __syncthreads();

        if (hasWork && chunk < segEnd && chunkEnd > pos) {
            ull acc[32];
#pragma unroll
            for (int j = 0; j < 32; j++) acc[j] = 0ull;

            const float* xb = xw + hh * 16;
#pragma unroll 4
            for (int i = 0; i < H_DIM; i++) {
                float4 w = W4s[i * 16 + t];
                ull w0, w1, w2, w3;
                DUP2(w0, w.x); DUP2(w1, w.y); DUP2(w2, w.z); DUP2(w3, w.w);
                const float* xi = xb + i * XT_STRIDE;
#pragma unroll
                for (int q = 0; q < 4; q++) {
                    ulonglong2 xv = *(const ulonglong2*)(xi + q * 4);
                    FMA2(acc[(2 * q) * 4 + 0], xv.x, w0);
                    FMA2(acc[(2 * q) * 4 + 1], xv.x, w1);
                    FMA2(acc[(2 * q) * 4 + 2], xv.x, w2);
                    FMA2(acc[(2 * q) * 4 + 3], xv.x, w3);
                    FMA2(acc[(2 * q + 1) * 4 + 0], xv.y, w0);
                    FMA2(acc[(2 * q + 1) * 4 + 1], xv.y, w1);
                    FMA2(acc[(2 * q + 1) * 4 + 2], xv.y, w2);
                    FMA2(acc[(2 * q + 1) * 4 + 3], xv.y, w3);
                }
            }

#pragma unroll
            for (int k = 0; k < 16; k++) {
                int  le   = hh * 16 + k;
                int  gke  = chunk + le;
                int  dstE = __shfl_sync(0xffffffffu, ed.y, le);
                bool doit = (gke >= pos) && (gke < segEnd);
                if (doit) {
                    float* hp = h + dstE * H_DIM + t;
                    int pp = k >> 1, c = k & 1;
#pragma unroll
                    for (int q = 0; q < 4; q++) {
                        float f0, f1;
                        UNPK2(f0, f1, acc[pp * 4 + q]);
                        float val = c ? f1 : f0;
                        asm volatile("red.global.add.f32 [%0], %1;"
                                     :: "l"(hp + q * 16), "f"(val) : "memory");
                    }
                }
            }
        }
        pos = segEnd;
    }
}

// ---------------- edge kernel, H->OUT: 2 edges/thread, relu fused ----------
// 512 edges/block; thread owns edges base+2*tid, +1. W loads shared across
// both edges (4 broadcast LDS.128 per i for 2 edges). Norm applied at end.
// Boundary-straddling edges recomputed in their own segment, emit masked.
__global__ void __launch_bounds__(256, 4) k_edge16(const float* __restrict__ x,
                                                   const float* __restrict__ W,
                                                   float* __restrict__ h) {
    __shared__ float Ws[H_DIM * OUT_DIM];
    const int tid  = threadIdx.x;
    int base = blockIdx.x * 512;
    int lim  = min(base + 512, E_EDGES);

    int e0 = base + tid * 2;
    int e1 = e0 + 1;
    int4 ed0 = g_edges[min(e0, lim - 1)];
    int4 ed1 = g_edges[min(e1, lim - 1)];
    const float* x0 = x + ed0.x * H_DIM;
    const float* x1 = x + ed1.x * H_DIM;

    int pos = base;
    while (pos < lim) {
        int r      = ((const int*)g_edges)[pos * 4 + 2];
        int segEnd = min(lim, g_off[r + 1]);
        __syncthreads();
        ((float4*)Ws)[tid] = ((const float4*)(W + r * (H_DIM * OUT_DIM)))[tid];
        __syncthreads();

        if (e0 < segEnd && e1 >= pos && e0 < lim) {
            ull acc[16];
#pragma unroll
            for (int j = 0; j < 16; j++) acc[j] = 0ull;

            for (int ic = 0; ic < 8; ic++) {
                float4 a0 = *(const float4*)(x0 + ic * 8);
                float4 a1 = *(const float4*)(x0 + ic * 8 + 4);
                float4 b0 = *(const float4*)(x1 + ic * 8);
                float4 b1 = *(const float4*)(x1 + ic * 8 + 4);
#pragma unroll
                for (int i = 0; i < 8; i++) {
                    const float* Wrow = Ws + (ic * 8 + i) * OUT_DIM;
                    ulonglong2 wA = *(const ulonglong2*)(Wrow);
                    ulonglong2 wB = *(const ulonglong2*)(Wrow + 4);
                    ulonglong2 wC = *(const ulonglong2*)(Wrow + 8);
                    ulonglong2 wD = *(const ulonglong2*)(Wrow + 12);
                    float xi0 = (i < 4) ? ((const float*)&a0)[i] : ((const float*)&a1)[i - 4];
                    float xi1 = (i < 4) ? ((const float*)&b0)[i] : ((const float*)&b1)[i - 4];
                    ull A0, A1;
                    DUP2(A0, fmaxf(xi0, 0.f));    // relu fused (prev layer)
                    DUP2(A1, fmaxf(xi1, 0.f));
                    FMA2(acc[0], A0, wA.x); FMA2(acc[1], A0, wA.y);
                    FMA2(acc[2], A0, wB.x); FMA2(acc[3], A0, wB.y);
                    FMA2(acc[4], A0, wC.x); FMA2(acc[5], A0, wC.y);
                    FMA2(acc[6], A0, wD.x); FMA2(acc[7], A0, wD.y);
                    FMA2(acc[8],  A1, wA.x); FMA2(acc[9],  A1, wA.y);
                    FMA2(acc[10], A1, wB.x); FMA2(acc[11], A1, wB.y);
                    FMA2(acc[12], A1, wC.x); FMA2(acc[13], A1, wC.y);
                    FMA2(acc[14], A1, wD.x); FMA2(acc[15], A1, wD.y);
                }
            }

            if (e0 >= pos && e0 < segEnd) {
                ull N0; DUP2(N0, __int_as_float(ed0.w));
                float* hp = h + ed0.y * OUT_DIM;
#pragma unroll
                for (int q = 0; q < 4; q++) {
                    MUL2(acc[2 * q], N0); MUL2(acc[2 * q + 1], N0);
                    float f0, f1, f2, f3;
                    UNPK2(f0, f1, acc[2 * q]);
                    UNPK2(f2, f3, acc[2 * q + 1]);
                    asm volatile("red.global.add.v4.f32 [%0], {%1, %2, %3, %4};"
                                 :: "l"(hp + q * 4), "f"(f0), "f"(f1), "f"(f2), "f"(f3)
                                 : "memory");
                }
            }
            if (e1 >= pos && e1 < segEnd) {
                ull N1; DUP2(N1, __int_as_float(ed1.w));
                float* hp = h + ed1.y * OUT_DIM;
#pragma unroll
                for (int q = 0; q < 4; q++) {
                    MUL2(acc[8 + 2 * q], N1); MUL2(acc[8 + 2 * q + 1], N1);
                    float f0, f1, f2, f3;
                    UNPK2(f0, f1, acc[8 + 2 * q]);
                    UNPK2(f2, f3, acc[8 + 2 * q + 1]);
                    asm volatile("red.global.add.v4.f32 [%0], {%1, %2, %3, %4};"
                                 :: "l"(hp + q * 4), "f"(f0), "f"(f1), "f"(f2), "f"(f3)
                                 : "memory");
                }
            }
        }
        pos = segEnd;
    }
}

// ---------------- launch ----------------
extern "C" void kernel_launch(void* const* d_in, const int* in_sizes, int n_in,
                              void* d_out, int out_size) {
    const float* feats  = (const float*)d_in[0];
    const float* coeff0 = (const float*)d_in[1];
    const float* bases0 = (const float*)d_in[2];
    const float* bias0  = (const float*)d_in[3];
    const float* coeff1 = (const float*)d_in[4];
    const float* bases1 = (const float*)d_in[5];
    const float* bias1  = (const float*)d_in[6];
    const float* coeff2 = (const float*)d_in[7];
    const float* bases2 = (const float*)d_in[8];
    const float* bias2  = (const float*)d_in[9];
    const int*   src    = (const int*)d_in[10];
    const int*   dst    = (const int*)d_in[11];
    const int*   etype  = (const int*)d_in[12];
    const float* norm   = (const float*)d_in[13];
    float*       out    = (float*)d_out;

    const int EB   = (E_EDGES + 255) / 256;
    const int EB16 = (E_EDGES + 511) / 512;
    const int PREP_BLKS = SB_BLKS + (FLAT_TOT + 255) / 256;

    float *h1, *h2, *W2;
    float4 *W40, *W41;
    cudaGetSymbolAddress((void**)&h1,  g_h1);
    cudaGetSymbolAddress((void**)&h2,  g_h2);
    cudaGetSymbolAddress((void**)&W40, g_W40);
    cudaGetSymbolAddress((void**)&W41, g_W41);
    cudaGetSymbolAddress((void**)&W2,  g_W2);

    cudaFuncSetAttribute(k_edge64<false>,
                         cudaFuncAttributeMaxDynamicSharedMemorySize, SMEM_E64);
    cudaFuncSetAttribute(k_edge64<true>,
                         cudaFuncAttributeMaxDynamicSharedMemorySize, SMEM_E64);

    k_prep<<<PREP_BLKS, 256>>>(etype, coeff0, bases0, coeff1, bases1,
                               coeff2, bases2, bias0, bias1, bias2, out);
    k_scan2<<<1, 1024>>>();
    k_scatter<<<SB_BLKS, 256>>>(src, dst, etype, norm);
    // 4th launch -> ncu window
    k_edge64<false><<<EB, 256, SMEM_E64>>>(feats, W40, h1);
    k_edge64<true><<<EB, 256, SMEM_E64>>>(h1, W41, h2);
    k_edge16<<<EB16, 256>>>(h2, W2, out);
}